// round 7
// baseline (speedup 1.0000x reference)
#include <cuda_runtime.h>
#include <math.h>
#include <stdint.h>

#define VOCAB 32000
#define EMB 256
#define HID 256
#define BATCH 64
#define SEQT 2048

// Scratch: V[v][j] = sum_e emb[v][e]*W_ih[e][j] + b_ih[j] + b_hh[j]  (32 MB, L2-resident)
__device__ float g_V[VOCAB * HID];

// ---------------------------------------------------------------------------
// f32x2 packed helpers (PTX-only; ptxas won't auto-fuse)
// ---------------------------------------------------------------------------
__device__ __forceinline__ unsigned long long pack2(float lo, float hi) {
    unsigned long long r;
    asm("mov.b64 %0, {%1, %2};" : "=l"(r) : "f"(lo), "f"(hi));
    return r;
}
__device__ __forceinline__ void fma2(unsigned long long& acc,
                                     unsigned long long a, unsigned long long b) {
    asm("fma.rn.f32x2 %0, %1, %2, %0;" : "+l"(acc) : "l"(a), "l"(b));
}
__device__ __forceinline__ unsigned long long add2(unsigned long long a,
                                                   unsigned long long b) {
    unsigned long long r;
    asm("add.rn.f32x2 %0, %1, %2;" : "=l"(r) : "l"(a), "l"(b));
    return r;
}
__device__ __forceinline__ void unpack2(unsigned long long v, float& lo, float& hi) {
    asm("mov.b64 {%0, %1}, %2;" : "=f"(lo), "=f"(hi) : "l"(v));
}
__device__ __forceinline__ unsigned long long shfl_bfly_u64(unsigned long long v,
                                                            int mask) {
    uint32_t lo = (uint32_t)v, hi = (uint32_t)(v >> 32);
    lo = __shfl_xor_sync(0xffffffffu, lo, mask);
    hi = __shfl_xor_sync(0xffffffffu, hi, mask);
    return ((unsigned long long)hi << 32) | lo;
}

// ---------------------------------------------------------------------------
// Kernel 1: vocab projection GEMM  [32000,256] x [256,256] + bias  (f32x2)
// ---------------------------------------------------------------------------
__global__ void __launch_bounds__(256) vocab_proj_kernel(
    const float* __restrict__ emb, const float* __restrict__ W_ih,
    const float* __restrict__ b_ih, const float* __restrict__ b_hh)
{
    __shared__ float As_T[32][68];
    const int row0 = blockIdx.x * 64;
    const int j = threadIdx.x;

    const float bias = b_ih[j] + b_hh[j];

    unsigned long long acc[32];
#pragma unroll
    for (int p = 0; p < 32; p++) acc[p] = 0ull;

#pragma unroll 1
    for (int k0 = 0; k0 < EMB; k0 += 32) {
        __syncthreads();
#pragma unroll
        for (int it = 0; it < 8; it++) {
            int idx = it * 256 + threadIdx.x;
            int r  = idx >> 5;
            int kk = idx & 31;
            As_T[kk][r] = emb[(size_t)(row0 + r) * EMB + (k0 + kk)];
        }
        __syncthreads();

        float wt[32];
#pragma unroll
        for (int kk = 0; kk < 32; kk++)
            wt[kk] = W_ih[(size_t)(k0 + kk) * HID + j];

#pragma unroll
        for (int kk = 0; kk < 32; kk++) {
            unsigned long long ws = pack2(wt[kk], wt[kk]);
#pragma unroll
            for (int rp2 = 0; rp2 < 16; rp2++) {
                ulonglong2 av = *(const ulonglong2*)&As_T[kk][4 * rp2];
                fma2(acc[2 * rp2 + 0], av.x, ws);
                fma2(acc[2 * rp2 + 1], av.y, ws);
            }
        }
    }

#pragma unroll
    for (int p = 0; p < 32; p++) {
        float lo, hi;
        unpack2(acc[p], lo, hi);
        g_V[(size_t)(row0 + 2 * p + 0) * HID + j] = lo + bias;
        g_V[(size_t)(row0 + 2 * p + 1) * HID + j] = hi + bias;
    }
}

// ---------------------------------------------------------------------------
// Kernel 2: recurrence, SINGLE CTA per chain (no cluster, no DSMEM).
// 256 threads. Thread (warp w, lane l): kg = l&3 -> k in [64*kg, 64*kg+64),
// cl = l>>2; owns 4 columns c_i = 32w + 8i + cl.
// W: per (col,i): k-rows [64kg, 64kg+52) in regs (104 f32x2), rows
// [64kg+52, 64kg+64) in per-thread SMEM scratch (48 floats, conflict-free).
// h: SMEM, 4 bank-staggered groups of (64+4) floats; LDS.128 serves all 4
// kg-groups in one wavefront. Cross-lane reduce: 2 bfly rounds over 4 lanes.
// ---------------------------------------------------------------------------
#define KREGP 26   // k-pairs per column in registers (52 k's)
#define GSTR  68   // floats per h group (64 + 4 pad -> bank stagger)
#define WSM_TH 52  // floats of W scratch per thread (48 used + 4 pad)

__global__ void __launch_bounds__(256, 1)
rnn_kernel(const int* __restrict__ source, const float* __restrict__ W_hh,
           float* __restrict__ out)
{
    extern __shared__ float sm[];
    float* Wsm  = sm;                               // 256*52 floats = 53248 B
    float* hbuf = sm + 256 * WSM_TH;                // 2 * 4*68 floats
    int*   srcs = (int*)(hbuf + 2 * 4 * GSTR);      // 2048 ints

    const int t  = threadIdx.x;
    const int w  = t >> 5;
    const int l  = t & 31;
    const int kg = l & 3;
    const int cl = l >> 2;
    const int b  = blockIdx.x;
    const int kb = kg * 64;                 // lane's k-range base
    const int cown = 32 * w + 8 * kg + cl;  // column this lane finalizes

    // Load source indices
    for (int i = t; i < SEQT; i += 256) srcs[i] = source[b * SEQT + i];

    // Zero both h buffers
    for (int i = t; i < 2 * 4 * GSTR; i += 256) hbuf[i] = 0.0f;

    // ---- Register-resident W: wr[i*26+kk] = (W[kb+2kk][c_i], W[kb+2kk+1][c_i])
    unsigned long long wr[4 * KREGP];
#pragma unroll
    for (int i = 0; i < 4; i++) {
        const int c = 32 * w + 8 * i + cl;
#pragma unroll
        for (int kk = 0; kk < KREGP; kk++)
            wr[i * KREGP + kk] = pack2(W_hh[(size_t)(kb + 2 * kk + 0) * HID + c],
                                       W_hh[(size_t)(kb + 2 * kk + 1) * HID + c]);
    }

    // ---- SMEM-resident W: per thread 4 cols x 12 k-rows [kb+52, kb+64)
    {
        float* wp = Wsm + t * WSM_TH;
#pragma unroll
        for (int i = 0; i < 4; i++) {
            const int c = 32 * w + 8 * i + cl;
#pragma unroll
            for (int m = 0; m < 12; m++)
                wp[i * 12 + m] = W_hh[(size_t)(kb + 52 + m) * HID + c];
        }
    }

    __syncthreads();

    const float* wsm_t = Wsm + t * WSM_TH;
    float hval = 0.0f;

#pragma unroll 1
    for (int step = 0; step < SEQT; step++) {
        const int cur = step & 1;

        // Prefetch x-projection for the column this lane finalizes
        const int idx = srcs[step];
        const float xv = g_V[(size_t)idx * HID + cown];

        // h group base for this lane's k-slice (bank-staggered groups)
        const float* hg = hbuf + cur * (4 * GSTR) + kg * GSTR;

        unsigned long long a0 = 0, a1 = 0, a2 = 0, a3 = 0;

        // Register W part: k-pairs 0..25 of this lane's slice
        const ulonglong2* hp2 = (const ulonglong2*)hg;
#pragma unroll
        for (int q = 0; q < 13; q++) {
            ulonglong2 hh = hp2[q];   // k-pairs 2q, 2q+1 (1 wavefront: 4x16B)
            fma2(a0, hh.x, wr[0 * KREGP + 2 * q]); fma2(a0, hh.y, wr[0 * KREGP + 2 * q + 1]);
            fma2(a1, hh.x, wr[1 * KREGP + 2 * q]); fma2(a1, hh.y, wr[1 * KREGP + 2 * q + 1]);
            fma2(a2, hh.x, wr[2 * KREGP + 2 * q]); fma2(a2, hh.y, wr[2 * KREGP + 2 * q + 1]);
            fma2(a3, hh.x, wr[3 * KREGP + 2 * q]); fma2(a3, hh.y, wr[3 * KREGP + 2 * q + 1]);
        }

        // SMEM W part: k-rows [kb+52, kb+64) = 3 ulonglong2 of h, 3 per col of W
        {
            const ulonglong2* hsm = (const ulonglong2*)(hg + 52);
            const ulonglong2* wv  = (const ulonglong2*)wsm_t;
#pragma unroll
            for (int q = 0; q < 3; q++) {
                ulonglong2 hh = hsm[q];
                ulonglong2 w0 = wv[0 * 3 + q];
                ulonglong2 w1 = wv[1 * 3 + q];
                ulonglong2 w2 = wv[2 * 3 + q];
                ulonglong2 w3 = wv[3 * 3 + q];
                fma2(a0, hh.x, w0.x); fma2(a0, hh.y, w0.y);
                fma2(a1, hh.x, w1.x); fma2(a1, hh.y, w1.y);
                fma2(a2, hh.x, w2.x); fma2(a2, hh.y, w2.y);
                fma2(a3, hh.x, w3.x); fma2(a3, hh.y, w3.y);
            }
        }

        // Per-column partial sums (lo+hi), packed for the bfly reduce
        float s0lo, s0hi, s1lo, s1hi, s2lo, s2hi, s3lo, s3hi;
        unpack2(a0, s0lo, s0hi); unpack2(a1, s1lo, s1hi);
        unpack2(a2, s2lo, s2hi); unpack2(a3, s3lo, s3hi);
        unsigned long long p01 = pack2(s0lo + s0hi, s1lo + s1hi);
        unsigned long long p23 = pack2(s2lo + s2hi, s3lo + s3hi);

        // Reduce across the 4 kg-lanes (xor 1, xor 2)
        p01 = add2(p01, shfl_bfly_u64(p01, 1));
        p23 = add2(p23, shfl_bfly_u64(p23, 1));
        p01 = add2(p01, shfl_bfly_u64(p01, 2));
        p23 = add2(p23, shfl_bfly_u64(p23, 2));

        // Lane kg finalizes column c_kg = 32w + 8*kg + cl
        float f0, f1, f2, f3;
        unpack2(p01, f0, f1);
        unpack2(p23, f2, f3);
        float mine = (kg == 0) ? f0 : (kg == 1) ? f1 : (kg == 2) ? f2 : f3;

        float pre = xv + mine;
        float e = __expf(2.0f * pre);
        hval = 1.0f - __fdividef(2.0f, e + 1.0f);

        // Store h for next step: group (cown>>6), staggered layout
        hbuf[(cur ^ 1) * (4 * GSTR) + (cown >> 6) * GSTR + (cown & 63)] = hval;

        __syncthreads();
    }

    out[b * HID + cown] = hval;
}

// ---------------------------------------------------------------------------
extern "C" void kernel_launch(void* const* d_in, const int* in_sizes, int n_in,
                              void* d_out, int out_size)
{
    const int*   source    = (const int*)d_in[0];
    const float* embedding = (const float*)d_in[1];
    const float* W_ih      = (const float*)d_in[2];
    const float* W_hh      = (const float*)d_in[3];
    const float* b_ih      = (const float*)d_in[4];
    const float* b_hh      = (const float*)d_in[5];
    float* out = (float*)d_out;

    const int smem_bytes = (256 * WSM_TH + 2 * 4 * GSTR) * 4 + SEQT * 4;  // ~63.7 KB
    cudaFuncSetAttribute(rnn_kernel,
                         cudaFuncAttributeMaxDynamicSharedMemorySize,
                         smem_bytes);

    vocab_proj_kernel<<<VOCAB / 64, 256>>>(embedding, W_ih, b_ih, b_hh);
    rnn_kernel<<<BATCH, 256, smem_bytes>>>(source, W_hh, out);
}